// round 10
// baseline (speedup 1.0000x reference)
#include <cuda_runtime.h>
#include <math.h>
#include <stdint.h>

#define NB      4
#define IN_CHAN 128
#define HW      3136
#define HWP     3328      // 26*128 = 13*256 = 52*64
#define OC      32
#define QC      8
#define D       16
#define JSPLIT  14
#define JLEN    (HW / JSPLIT)   // 224
#define TJ      32
#define NT      (JLEN / TJ)     // 7 tiles
#define BN_EPS  1e-5f
#define QPIX    64
#define LOG2E   1.44269504088896340736f

#define SB_STRIDE 20
#define SP_STRIDE 36

// ---------------- scratch (device globals; no allocation allowed) ----------------
__device__ __align__(16) float g_A[NB][HWP][D];                 // log2e*[q+rk ; rq]
__device__ __align__(16) float g_B[NB][HWP][D];                 // [k ; q]
__device__ __align__(16) float g_V[NB][HWP][D];                 // v + rv
__device__ __align__(16) float g_pacc[JSPLIT][NB][HWP][D];      // partial sum(e^s * v)
__device__ __align__(16) float g_pl[JSPLIT][NB][HWP];           // partial sum(e^s)

// ---------------- tf32 mma helpers ----------------
__device__ __forceinline__ uint32_t f2tf(float f) {
    uint32_t r; asm("cvt.rna.tf32.f32 %0, %1;" : "=r"(r) : "f"(f)); return r;
}
__device__ __forceinline__ float ex2f(float x) {
    float r; asm("ex2.approx.ftz.f32 %0, %1;" : "=f"(r) : "f"(x)); return r;
}
__device__ __forceinline__ void mma8(float* d, const uint32_t* a, const uint32_t* b) {
    asm("mma.sync.aligned.m16n8k8.row.col.f32.tf32.tf32.f32 "
        "{%0,%1,%2,%3}, {%4,%5,%6,%7}, {%8,%9}, {%0,%1,%2,%3};"
        : "+f"(d[0]), "+f"(d[1]), "+f"(d[2]), "+f"(d[3])
        : "r"(a[0]), "r"(a[1]), "r"(a[2]), "r"(a[3]), "r"(b[0]), "r"(b[1]));
}
__device__ __forceinline__ void tfsplit(float x, uint32_t& hi, uint32_t& lo) {
    hi = f2tf(x);
    lo = f2tf(x - __uint_as_float(hi));
}

// ======================================================================
// Kernel 1: QKV 1x1 conv + BN + build A/B/V (A pre-scaled by log2e).
// SMEM-staged x-tile: coop load sx[128][64] (8 indep float4 LDG/thread,
// latency paid once), then FMA from smem with only acc[8] live -> no
// spills (the diagnosed killer of all previous qkv versions).
// No cross-thread reduction needed: each thread does all 128 channels.
// ======================================================================
__global__ __launch_bounds__(256)
void qkv_kernel(const float* __restrict__ x, const float* __restrict__ w,
                const float* __restrict__ bq, const float* __restrict__ gamma,
                const float* __restrict__ beta, const float* __restrict__ mean,
                const float* __restrict__ var,
                const float* __restrict__ rq, const float* __restrict__ rk,
                const float* __restrict__ rv)
{
    __shared__ float sx[IN_CHAN][QPIX];          // 32 KB x tile
    __shared__ float sw[IN_CHAN][OC];            // 16 KB transposed weights
    __shared__ float sscale[OC], sbias[OC];
    __shared__ float sr[QPIX][OC + 1];           // post-BN qkv

    const int tid = threadIdx.x;
    const int p   = tid & (QPIX - 1);
    const int qd  = tid >> 6;                    // o-octet / epilogue segment

    const int n    = blockIdx.y;
    const int pix0 = blockIdx.x * QPIX;
    const bool live = (pix0 < HW);               // whole block live or dead (3136=49*64)

    // weights + BN constants
    for (int idx = tid; idx < IN_CHAN * OC; idx += 256) {
        int o = idx & (OC - 1), c = idx >> 5;
        sw[c][o] = w[o * IN_CHAN + c];
    }
    if (tid < OC) {
        float sc = gamma[tid] * rsqrtf(var[tid] + BN_EPS);
        sscale[tid] = sc;
        sbias[tid]  = (bq[tid] - mean[tid]) * sc + beta[tid];
    }

    // cooperative x-tile load: 128 rows x 16 float4 = 2048 float4, 8/thread
    if (live) {
        const float* xb = x + (size_t)n * IN_CHAN * HW + pix0;
        #pragma unroll
        for (int k = 0; k < 8; k++) {
            int i = k * 256 + tid;               // 0..2047
            int c = i >> 4, j = (i & 15) * 4;
            *reinterpret_cast<float4*>(&sx[c][j]) =
                *reinterpret_cast<const float4*>(xb + (size_t)c * HW + j);
        }
    }
    __syncthreads();

    if (live) {
        const int obase = qd * 8;
        float acc[8];
        #pragma unroll
        for (int k = 0; k < 8; k++) acc[k] = 0.f;

        #pragma unroll 4
        for (int c = 0; c < IN_CHAN; c++) {
            const float xs = sx[c][p];
            float4 wa = *reinterpret_cast<const float4*>(&sw[c][obase]);
            float4 wb = *reinterpret_cast<const float4*>(&sw[c][obase + 4]);
            acc[0] = fmaf(xs, wa.x, acc[0]);
            acc[1] = fmaf(xs, wa.y, acc[1]);
            acc[2] = fmaf(xs, wa.z, acc[2]);
            acc[3] = fmaf(xs, wa.w, acc[3]);
            acc[4] = fmaf(xs, wb.x, acc[4]);
            acc[5] = fmaf(xs, wb.y, acc[5]);
            acc[6] = fmaf(xs, wb.z, acc[6]);
            acc[7] = fmaf(xs, wb.w, acc[7]);
        }
        #pragma unroll
        for (int k = 0; k < 8; k++)
            sr[p][obase + k] = fmaf(acc[k], sscale[obase + k], sbias[obase + k]);
    }
    __syncthreads();

    // ---- segmented epilogue (seg = qd): build A/B/V rows ----
    const int gpix = pix0 + p;
    if (live) {
        if (qd == 0) {               // A[0..7] = log2e*(q + rk)
            float av[8];
            #pragma unroll
            for (int c = 0; c < 8; c++)
                av[c] = LOG2E * (sr[p][c] + __ldg(rk + (size_t)c * HW + gpix));
            reinterpret_cast<float4*>(&g_A[n][gpix][0])[0] = reinterpret_cast<float4*>(av)[0];
            reinterpret_cast<float4*>(&g_A[n][gpix][0])[1] = reinterpret_cast<float4*>(av)[1];
        } else if (qd == 1) {        // A[8..15] = log2e*rq
            float av[8];
            #pragma unroll
            for (int c = 0; c < 8; c++)
                av[c] = LOG2E * __ldg(rq + (size_t)c * HW + gpix);
            reinterpret_cast<float4*>(&g_A[n][gpix][8])[0] = reinterpret_cast<float4*>(av)[0];
            reinterpret_cast<float4*>(&g_A[n][gpix][8])[1] = reinterpret_cast<float4*>(av)[1];
        } else if (qd == 2) {        // B = [k ; q]
            float bv[16];
            #pragma unroll
            for (int c = 0; c < 8; c++) { bv[c] = sr[p][QC + c]; bv[QC + c] = sr[p][c]; }
            #pragma unroll
            for (int q4 = 0; q4 < 4; q4++)
                reinterpret_cast<float4*>(&g_B[n][gpix][0])[q4] = reinterpret_cast<float4*>(bv)[q4];
        } else {                     // V = v + rv
            float vv[16];
            #pragma unroll
            for (int c = 0; c < 16; c++)
                vv[c] = sr[p][2 * QC + c] + __ldg(rv + (size_t)c * HW + gpix);
            #pragma unroll
            for (int q4 = 0; q4 < 4; q4++)
                reinterpret_cast<float4*>(&g_V[n][gpix][0])[q4] = reinterpret_cast<float4*>(vv)[q4];
        }
    } else {
        float4 z = make_float4(0.f, 0.f, 0.f, 0.f);
        if (qd == 0) {
            reinterpret_cast<float4*>(&g_A[n][gpix][0])[0] = z;
            reinterpret_cast<float4*>(&g_A[n][gpix][0])[1] = z;
        } else if (qd == 1) {
            reinterpret_cast<float4*>(&g_A[n][gpix][8])[0] = z;
            reinterpret_cast<float4*>(&g_A[n][gpix][8])[1] = z;
        } else if (qd == 2) {
            #pragma unroll
            for (int q4 = 0; q4 < 4; q4++)
                reinterpret_cast<float4*>(&g_B[n][gpix][0])[q4] = z;
        } else {
            #pragma unroll
            for (int q4 = 0; q4 < 4; q4++)
                reinterpret_cast<float4*>(&g_V[n][gpix][0])[q4] = z;
        }
    }
}

// ======================================================================
// Kernel 2: tensor-core attention (unchanged from R9).
//   scores: tf32 x3 compensated   AV: tf32 x1 with l over rounded P
// ======================================================================
__global__ __launch_bounds__(128)
void attn_kernel()
{
    __shared__ __align__(16) float sBh[TJ][SB_STRIDE], sBl[TJ][SB_STRIDE];
    __shared__ __align__(16) float sVh[TJ][SB_STRIDE];
    __shared__ float sp[128][SP_STRIDE];

    const int tid   = threadIdx.x;
    const int warp  = tid >> 5;
    const int lane  = tid & 31;
    const int g     = lane >> 2;
    const int tg    = lane & 3;
    const int itile = blockIdx.x;
    const int js    = blockIdx.y;
    const int n     = blockIdx.z;
    const int i0    = itile * 128;
    const int wbase = warp * 32;
    const int jbase = js * JLEN;

    const int lr  = tid >> 2;
    const int lc4 = (tid & 3) * 4;

    uint32_t ah[2][2][4], al[2][2][4];
    #pragma unroll
    for (int mg = 0; mg < 2; mg++)
        #pragma unroll
        for (int ks = 0; ks < 2; ks++)
            #pragma unroll
            for (int r = 0; r < 4; r++) {
                int row = i0 + wbase + mg * 16 + g + ((r & 1) ? 8 : 0);
                int col = ks * 8 + tg + ((r & 2) ? 4 : 0);
                tfsplit(g_A[n][row][col], ah[mg][ks][r], al[mg][ks][r]);
            }

    float co[2][2][4];
    #pragma unroll
    for (int mg = 0; mg < 2; mg++)
        #pragma unroll
        for (int nt = 0; nt < 2; nt++)
            #pragma unroll
            for (int r = 0; r < 4; r++) co[mg][nt][r] = 0.f;
    float L[2][2] = {{0.f, 0.f}, {0.f, 0.f}};

    for (int t = 0; t < NT; t++) {
        const int j0 = jbase + t * TJ;
        {
            float4 b = *reinterpret_cast<const float4*>(&g_B[n][j0 + lr][lc4]);
            float4 v = *reinterpret_cast<const float4*>(&g_V[n][j0 + lr][lc4]);
            uint32_t h, l;
            tfsplit(b.x, h, l); sBh[lr][lc4+0] = __uint_as_float(h); sBl[lr][lc4+0] = __uint_as_float(l);
            tfsplit(b.y, h, l); sBh[lr][lc4+1] = __uint_as_float(h); sBl[lr][lc4+1] = __uint_as_float(l);
            tfsplit(b.z, h, l); sBh[lr][lc4+2] = __uint_as_float(h); sBl[lr][lc4+2] = __uint_as_float(l);
            tfsplit(b.w, h, l); sBh[lr][lc4+3] = __uint_as_float(h); sBl[lr][lc4+3] = __uint_as_float(l);
            sVh[lr][lc4+0] = __uint_as_float(f2tf(v.x));
            sVh[lr][lc4+1] = __uint_as_float(f2tf(v.y));
            sVh[lr][lc4+2] = __uint_as_float(f2tf(v.z));
            sVh[lr][lc4+3] = __uint_as_float(f2tf(v.w));
        }
        __syncthreads();

        float cs[2][4][4];
        #pragma unroll
        for (int mg = 0; mg < 2; mg++)
            #pragma unroll
            for (int nt = 0; nt < 4; nt++)
                #pragma unroll
                for (int r = 0; r < 4; r++) cs[mg][nt][r] = 0.f;

        #pragma unroll
        for (int ks = 0; ks < 2; ks++) {
            uint32_t bh[4][2], bl[4][2];
            #pragma unroll
            for (int nt = 0; nt < 4; nt++)
                #pragma unroll
                for (int rr = 0; rr < 2; rr++) {
                    bh[nt][rr] = __float_as_uint(sBh[nt * 8 + g][ks * 8 + tg + rr * 4]);
                    bl[nt][rr] = __float_as_uint(sBl[nt * 8 + g][ks * 8 + tg + rr * 4]);
                }
            #pragma unroll
            for (int mg = 0; mg < 2; mg++)
                #pragma unroll
                for (int nt = 0; nt < 4; nt++) {
                    mma8(cs[mg][nt], ah[mg][ks], bh[nt]);
                    mma8(cs[mg][nt], al[mg][ks], bh[nt]);
                    mma8(cs[mg][nt], ah[mg][ks], bl[nt]);
                }
        }

        #pragma unroll
        for (int mg = 0; mg < 2; mg++) {
            float s0 = 0.f, s1 = 0.f;
            #pragma unroll
            for (int nt = 0; nt < 4; nt++) {
                float p0 = __uint_as_float(f2tf(ex2f(cs[mg][nt][0])));
                float p1 = __uint_as_float(f2tf(ex2f(cs[mg][nt][1])));
                float p2 = __uint_as_float(f2tf(ex2f(cs[mg][nt][2])));
                float p3 = __uint_as_float(f2tf(ex2f(cs[mg][nt][3])));
                s0 += p0 + p1;
                s1 += p2 + p3;
                int r0 = wbase + mg * 16 + g;
                int c  = nt * 8 + 2 * tg;
                *reinterpret_cast<float2*>(&sp[r0][c])     = make_float2(p0, p1);
                *reinterpret_cast<float2*>(&sp[r0 + 8][c]) = make_float2(p2, p3);
            }
            s0 += __shfl_xor_sync(0xffffffffu, s0, 1);
            s0 += __shfl_xor_sync(0xffffffffu, s0, 2);
            s1 += __shfl_xor_sync(0xffffffffu, s1, 1);
            s1 += __shfl_xor_sync(0xffffffffu, s1, 2);
            L[mg][0] += s0;
            L[mg][1] += s1;
        }
        __syncwarp();

        #pragma unroll
        for (int kj = 0; kj < 4; kj++) {
            uint32_t pah[2][4];
            #pragma unroll
            for (int mg = 0; mg < 2; mg++)
                #pragma unroll
                for (int r = 0; r < 4; r++) {
                    int row = wbase + mg * 16 + g + ((r & 1) ? 8 : 0);
                    int col = kj * 8 + tg + ((r & 2) ? 4 : 0);
                    pah[mg][r] = __float_as_uint(sp[row][col]);
                }
            uint32_t vh[2][2];
            #pragma unroll
            for (int nt = 0; nt < 2; nt++)
                #pragma unroll
                for (int rr = 0; rr < 2; rr++)
                    vh[nt][rr] = __float_as_uint(sVh[kj * 8 + tg + rr * 4][nt * 8 + g]);
            #pragma unroll
            for (int mg = 0; mg < 2; mg++)
                #pragma unroll
                for (int nt = 0; nt < 2; nt++)
                    mma8(co[mg][nt], pah[mg], vh[nt]);
        }
        __syncthreads();
    }

    #pragma unroll
    for (int mg = 0; mg < 2; mg++)
        #pragma unroll
        for (int nt = 0; nt < 2; nt++) {
            int r0 = i0 + wbase + mg * 16 + g;
            int c  = nt * 8 + 2 * tg;
            *reinterpret_cast<float2*>(&g_pacc[js][n][r0][c]) =
                make_float2(co[mg][nt][0], co[mg][nt][1]);
            *reinterpret_cast<float2*>(&g_pacc[js][n][r0 + 8][c]) =
                make_float2(co[mg][nt][2], co[mg][nt][3]);
        }
    if (tg == 0) {
        #pragma unroll
        for (int mg = 0; mg < 2; mg++) {
            g_pl[js][n][i0 + wbase + mg * 16 + g]     = L[mg][0];
            g_pl[js][n][i0 + wbase + mg * 16 + g + 8] = L[mg][1];
        }
    }
}

// ======================================================================
// Kernel 3: combine (unchanged from R9).
// ======================================================================
__global__ void combine_kernel(float* __restrict__ out)
{
    const int TOT  = NB * 2 * QC * 28 * 28;
    const int gidx = blockIdx.x * blockDim.x + threadIdx.x;
    if (gidx >= TOT * 4) return;
    const int e  = gidx >> 2;
    const int px = gidx & 3;

    int pw = e % 28;
    int t  = e / 28;
    int ph = t % 28; t /= 28;
    int c  = t % (2 * QC);
    int n  = t / (2 * QC);

    const int i = (2 * ph + (px >> 1)) * 56 + 2 * pw + (px & 1);

    float num = 0.f, den = 0.f;
    #pragma unroll
    for (int s = 0; s < JSPLIT; s++) {
        num += g_pacc[s][n][i][c];
        den += g_pl[s][n][i];
    }
    float r = num / den;
    r += __shfl_xor_sync(0xffffffffu, r, 1);
    r += __shfl_xor_sync(0xffffffffu, r, 2);
    if (px == 0) out[e] = 0.25f * r;
}

// ======================================================================
extern "C" void kernel_launch(void* const* d_in, const int* in_sizes, int n_in,
                              void* d_out, int out_size)
{
    const float* x     = (const float*)d_in[0];
    const float* w     = (const float*)d_in[1];
    const float* bq    = (const float*)d_in[2];
    const float* gamma = (const float*)d_in[3];
    const float* beta  = (const float*)d_in[4];
    const float* mean  = (const float*)d_in[5];
    const float* var   = (const float*)d_in[6];
    const float* rq    = (const float*)d_in[7];
    const float* rk    = (const float*)d_in[8];
    const float* rv    = (const float*)d_in[9];
    float* out = (float*)d_out;

    dim3 g1(HWP / QPIX, NB);          // (52, 4)
    qkv_kernel<<<g1, 256>>>(x, w, bq, gamma, beta, mean, var, rq, rk, rv);

    dim3 g2(HWP / 128, JSPLIT, NB);   // (26, 14, 4)
    attn_kernel<<<g2, 128>>>();

    const int TOT = NB * 2 * QC * 28 * 28;
    combine_kernel<<<(TOT * 4 + 255) / 256, 256>>>(out);
}

// round 11
// speedup vs baseline: 1.0068x; 1.0068x over previous
#include <cuda_runtime.h>
#include <math.h>
#include <stdint.h>

#define NB      4
#define IN_CHAN 128
#define HW      3136
#define HWP     3328      // 26*128 = 13*256 = 52*64
#define OC      32
#define QC      8
#define D       16
#define JSPLIT  14
#define JLEN    (HW / JSPLIT)   // 224
#define TJ      32
#define NT      (JLEN / TJ)     // 7 tiles
#define BN_EPS  1e-5f
#define QPIX    64
#define LOG2E   1.44269504088896340736f

#define SB_STRIDE 20
#define SP_STRIDE 36

// ---------------- scratch (device globals; no allocation allowed) ----------------
__device__ __align__(16) float g_A[NB][HWP][D];                 // log2e*[q+rk ; rq]
__device__ __align__(16) float g_B[NB][HWP][D];                 // [k ; q]
__device__ __align__(16) float g_V[NB][HWP][D];                 // v + rv
__device__ __align__(16) float g_pacc[JSPLIT][NB][HWP][D];      // partial sum(e^s * v)
__device__ __align__(16) float g_pl[JSPLIT][NB][HWP];           // partial sum(e^s)

// ---------------- helpers ----------------
__device__ __forceinline__ uint32_t f2tf(float f) {
    uint32_t r; asm("cvt.rna.tf32.f32 %0, %1;" : "=r"(r) : "f"(f)); return r;
}
__device__ __forceinline__ float ex2f(float x) {
    float r; asm("ex2.approx.ftz.f32 %0, %1;" : "=f"(r) : "f"(x)); return r;
}
__device__ __forceinline__ void mma8(float* d, const uint32_t* a, const uint32_t* b) {
    asm("mma.sync.aligned.m16n8k8.row.col.f32.tf32.tf32.f32 "
        "{%0,%1,%2,%3}, {%4,%5,%6,%7}, {%8,%9}, {%0,%1,%2,%3};"
        : "+f"(d[0]), "+f"(d[1]), "+f"(d[2]), "+f"(d[3])
        : "r"(a[0]), "r"(a[1]), "r"(a[2]), "r"(a[3]), "r"(b[0]), "r"(b[1]));
}
__device__ __forceinline__ void tfsplit(float x, uint32_t& hi, uint32_t& lo) {
    hi = f2tf(x);
    lo = f2tf(x - __uint_as_float(hi));
}
__device__ __forceinline__ void cpasync16(uint32_t saddr, const void* g) {
    asm volatile("cp.async.cg.shared.global [%0], [%1], 16;" :: "r"(saddr), "l"(g));
}
__device__ __forceinline__ void cpasync_wait_all() {
    asm volatile("cp.async.commit_group;\n\tcp.async.wait_group 0;" ::: "memory");
}

// ======================================================================
// Kernel 1: QKV 1x1 conv + BN + build A/B/V (A pre-scaled by log2e).
// ALL global reads (x tile + rk/rq/rv slices) issued as one cp.async
// burst (LDGSTS: no reg landing, full depth) -> exactly ONE exposed
// global latency per block. FMA + epilogue are then pure smem.
// ======================================================================
__global__ __launch_bounds__(256)
void qkv_kernel(const float* __restrict__ x, const float* __restrict__ w,
                const float* __restrict__ bq, const float* __restrict__ gamma,
                const float* __restrict__ beta, const float* __restrict__ mean,
                const float* __restrict__ var,
                const float* __restrict__ rq, const float* __restrict__ rk,
                const float* __restrict__ rv)
{
    __shared__ float sx[IN_CHAN][QPIX];          // 32 KB x tile
    __shared__ float sw[IN_CHAN][OC];            // 16 KB transposed weights
    __shared__ float srk[QC][QPIX];              // 2 KB
    __shared__ float srq[QC][QPIX];              // 2 KB
    __shared__ float srv[2 * QC][QPIX];          // 4 KB
    __shared__ float sscale[OC], sbias[OC];
    __shared__ float sr[QPIX][OC + 1];           // post-BN qkv

    const int tid = threadIdx.x;
    const int p   = tid & (QPIX - 1);
    const int qd  = tid >> 6;                    // o-octet / epilogue segment

    const int n    = blockIdx.y;
    const int pix0 = blockIdx.x * QPIX;
    const bool live = (pix0 < HW);               // uniform per block (3136 = 49*64)

    // ---- single cp.async burst: x tile + rk/rq/rv slices ----
    if (live) {
        const float* xb = x + (size_t)n * IN_CHAN * HW + pix0;
        #pragma unroll
        for (int k = 0; k < 8; k++) {
            int i = k * 256 + tid;               // 0..2047
            int c = i >> 4, j = (i & 15) * 4;
            cpasync16((uint32_t)__cvta_generic_to_shared(&sx[c][j]),
                      xb + (size_t)c * HW + j);
        }
        // 32 rows (rk 8, rq 8, rv 16) x 16 chunks = 512 chunks, 2/thread
        #pragma unroll
        for (int k = 0; k < 2; k++) {
            int i = k * 256 + tid;               // 0..511
            int row = i >> 4, j = (i & 15) * 4;
            const float* gsrc;
            float* sdst;
            if (row < 8)       { gsrc = rk + (size_t)row * HW + pix0 + j;        sdst = &srk[row][j]; }
            else if (row < 16) { gsrc = rq + (size_t)(row - 8) * HW + pix0 + j;  sdst = &srq[row - 8][j]; }
            else               { gsrc = rv + (size_t)(row - 16) * HW + pix0 + j; sdst = &srv[row - 16][j]; }
            cpasync16((uint32_t)__cvta_generic_to_shared(sdst), gsrc);
        }
    }

    // weights + BN constants (16KB, L2-hot across 208 blocks)
    for (int idx = tid; idx < IN_CHAN * OC; idx += 256) {
        int o = idx & (OC - 1), c = idx >> 5;
        sw[c][o] = w[o * IN_CHAN + c];
    }
    if (tid < OC) {
        float sc = gamma[tid] * rsqrtf(var[tid] + BN_EPS);
        sscale[tid] = sc;
        sbias[tid]  = (bq[tid] - mean[tid]) * sc + beta[tid];
    }

    if (live) cpasync_wait_all();
    __syncthreads();

    if (live) {
        const int obase = qd * 8;
        float acc[8];
        #pragma unroll
        for (int k = 0; k < 8; k++) acc[k] = 0.f;

        #pragma unroll 4
        for (int c = 0; c < IN_CHAN; c++) {
            const float xs = sx[c][p];
            float4 wa = *reinterpret_cast<const float4*>(&sw[c][obase]);
            float4 wb = *reinterpret_cast<const float4*>(&sw[c][obase + 4]);
            acc[0] = fmaf(xs, wa.x, acc[0]);
            acc[1] = fmaf(xs, wa.y, acc[1]);
            acc[2] = fmaf(xs, wa.z, acc[2]);
            acc[3] = fmaf(xs, wa.w, acc[3]);
            acc[4] = fmaf(xs, wb.x, acc[4]);
            acc[5] = fmaf(xs, wb.y, acc[5]);
            acc[6] = fmaf(xs, wb.z, acc[6]);
            acc[7] = fmaf(xs, wb.w, acc[7]);
        }
        #pragma unroll
        for (int k = 0; k < 8; k++)
            sr[p][obase + k] = fmaf(acc[k], sscale[obase + k], sbias[obase + k]);
    }
    __syncthreads();

    // ---- segmented epilogue (seg = qd): pure smem -> global stores ----
    const int gpix = pix0 + p;
    if (live) {
        if (qd == 0) {               // A[0..7] = log2e*(q + rk)
            float av[8];
            #pragma unroll
            for (int c = 0; c < 8; c++)
                av[c] = LOG2E * (sr[p][c] + srk[c][p]);
            reinterpret_cast<float4*>(&g_A[n][gpix][0])[0] = reinterpret_cast<float4*>(av)[0];
            reinterpret_cast<float4*>(&g_A[n][gpix][0])[1] = reinterpret_cast<float4*>(av)[1];
        } else if (qd == 1) {        // A[8..15] = log2e*rq
            float av[8];
            #pragma unroll
            for (int c = 0; c < 8; c++)
                av[c] = LOG2E * srq[c][p];
            reinterpret_cast<float4*>(&g_A[n][gpix][8])[0] = reinterpret_cast<float4*>(av)[0];
            reinterpret_cast<float4*>(&g_A[n][gpix][8])[1] = reinterpret_cast<float4*>(av)[1];
        } else if (qd == 2) {        // B = [k ; q]
            float bv[16];
            #pragma unroll
            for (int c = 0; c < 8; c++) { bv[c] = sr[p][QC + c]; bv[QC + c] = sr[p][c]; }
            #pragma unroll
            for (int q4 = 0; q4 < 4; q4++)
                reinterpret_cast<float4*>(&g_B[n][gpix][0])[q4] = reinterpret_cast<float4*>(bv)[q4];
        } else {                     // V = v + rv
            float vv[16];
            #pragma unroll
            for (int c = 0; c < 16; c++)
                vv[c] = sr[p][2 * QC + c] + srv[c][p];
            #pragma unroll
            for (int q4 = 0; q4 < 4; q4++)
                reinterpret_cast<float4*>(&g_V[n][gpix][0])[q4] = reinterpret_cast<float4*>(vv)[q4];
        }
    } else {
        float4 z = make_float4(0.f, 0.f, 0.f, 0.f);
        if (qd == 0) {
            reinterpret_cast<float4*>(&g_A[n][gpix][0])[0] = z;
            reinterpret_cast<float4*>(&g_A[n][gpix][0])[1] = z;
        } else if (qd == 1) {
            reinterpret_cast<float4*>(&g_A[n][gpix][8])[0] = z;
            reinterpret_cast<float4*>(&g_A[n][gpix][8])[1] = z;
        } else if (qd == 2) {
            #pragma unroll
            for (int q4 = 0; q4 < 4; q4++)
                reinterpret_cast<float4*>(&g_B[n][gpix][0])[q4] = z;
        } else {
            #pragma unroll
            for (int q4 = 0; q4 < 4; q4++)
                reinterpret_cast<float4*>(&g_V[n][gpix][0])[q4] = z;
        }
    }
}

// ======================================================================
// Kernel 2: tensor-core attention (UNCHANGED from R9/R10 best).
//   scores: tf32 x3 compensated   AV: tf32 x1 with l over rounded P
// ======================================================================
__global__ __launch_bounds__(128)
void attn_kernel()
{
    __shared__ __align__(16) float sBh[TJ][SB_STRIDE], sBl[TJ][SB_STRIDE];
    __shared__ __align__(16) float sVh[TJ][SB_STRIDE];
    __shared__ float sp[128][SP_STRIDE];

    const int tid   = threadIdx.x;
    const int warp  = tid >> 5;
    const int lane  = tid & 31;
    const int g     = lane >> 2;
    const int tg    = lane & 3;
    const int itile = blockIdx.x;
    const int js    = blockIdx.y;
    const int n     = blockIdx.z;
    const int i0    = itile * 128;
    const int wbase = warp * 32;
    const int jbase = js * JLEN;

    const int lr  = tid >> 2;
    const int lc4 = (tid & 3) * 4;

    uint32_t ah[2][2][4], al[2][2][4];
    #pragma unroll
    for (int mg = 0; mg < 2; mg++)
        #pragma unroll
        for (int ks = 0; ks < 2; ks++)
            #pragma unroll
            for (int r = 0; r < 4; r++) {
                int row = i0 + wbase + mg * 16 + g + ((r & 1) ? 8 : 0);
                int col = ks * 8 + tg + ((r & 2) ? 4 : 0);
                tfsplit(g_A[n][row][col], ah[mg][ks][r], al[mg][ks][r]);
            }

    float co[2][2][4];
    #pragma unroll
    for (int mg = 0; mg < 2; mg++)
        #pragma unroll
        for (int nt = 0; nt < 2; nt++)
            #pragma unroll
            for (int r = 0; r < 4; r++) co[mg][nt][r] = 0.f;
    float L[2][2] = {{0.f, 0.f}, {0.f, 0.f}};

    for (int t = 0; t < NT; t++) {
        const int j0 = jbase + t * TJ;
        {
            float4 b = *reinterpret_cast<const float4*>(&g_B[n][j0 + lr][lc4]);
            float4 v = *reinterpret_cast<const float4*>(&g_V[n][j0 + lr][lc4]);
            uint32_t h, l;
            tfsplit(b.x, h, l); sBh[lr][lc4+0] = __uint_as_float(h); sBl[lr][lc4+0] = __uint_as_float(l);
            tfsplit(b.y, h, l); sBh[lr][lc4+1] = __uint_as_float(h); sBl[lr][lc4+1] = __uint_as_float(l);
            tfsplit(b.z, h, l); sBh[lr][lc4+2] = __uint_as_float(h); sBl[lr][lc4+2] = __uint_as_float(l);
            tfsplit(b.w, h, l); sBh[lr][lc4+3] = __uint_as_float(h); sBl[lr][lc4+3] = __uint_as_float(l);
            sVh[lr][lc4+0] = __uint_as_float(f2tf(v.x));
            sVh[lr][lc4+1] = __uint_as_float(f2tf(v.y));
            sVh[lr][lc4+2] = __uint_as_float(f2tf(v.z));
            sVh[lr][lc4+3] = __uint_as_float(f2tf(v.w));
        }
        __syncthreads();

        float cs[2][4][4];
        #pragma unroll
        for (int mg = 0; mg < 2; mg++)
            #pragma unroll
            for (int nt = 0; nt < 4; nt++)
                #pragma unroll
                for (int r = 0; r < 4; r++) cs[mg][nt][r] = 0.f;

        #pragma unroll
        for (int ks = 0; ks < 2; ks++) {
            uint32_t bh[4][2], bl[4][2];
            #pragma unroll
            for (int nt = 0; nt < 4; nt++)
                #pragma unroll
                for (int rr = 0; rr < 2; rr++) {
                    bh[nt][rr] = __float_as_uint(sBh[nt * 8 + g][ks * 8 + tg + rr * 4]);
                    bl[nt][rr] = __float_as_uint(sBl[nt * 8 + g][ks * 8 + tg + rr * 4]);
                }
            #pragma unroll
            for (int mg = 0; mg < 2; mg++)
                #pragma unroll
                for (int nt = 0; nt < 4; nt++) {
                    mma8(cs[mg][nt], ah[mg][ks], bh[nt]);
                    mma8(cs[mg][nt], al[mg][ks], bh[nt]);
                    mma8(cs[mg][nt], ah[mg][ks], bl[nt]);
                }
        }

        #pragma unroll
        for (int mg = 0; mg < 2; mg++) {
            float s0 = 0.f, s1 = 0.f;
            #pragma unroll
            for (int nt = 0; nt < 4; nt++) {
                float p0 = __uint_as_float(f2tf(ex2f(cs[mg][nt][0])));
                float p1 = __uint_as_float(f2tf(ex2f(cs[mg][nt][1])));
                float p2 = __uint_as_float(f2tf(ex2f(cs[mg][nt][2])));
                float p3 = __uint_as_float(f2tf(ex2f(cs[mg][nt][3])));
                s0 += p0 + p1;
                s1 += p2 + p3;
                int r0 = wbase + mg * 16 + g;
                int c  = nt * 8 + 2 * tg;
                *reinterpret_cast<float2*>(&sp[r0][c])     = make_float2(p0, p1);
                *reinterpret_cast<float2*>(&sp[r0 + 8][c]) = make_float2(p2, p3);
            }
            s0 += __shfl_xor_sync(0xffffffffu, s0, 1);
            s0 += __shfl_xor_sync(0xffffffffu, s0, 2);
            s1 += __shfl_xor_sync(0xffffffffu, s1, 1);
            s1 += __shfl_xor_sync(0xffffffffu, s1, 2);
            L[mg][0] += s0;
            L[mg][1] += s1;
        }
        __syncwarp();

        #pragma unroll
        for (int kj = 0; kj < 4; kj++) {
            uint32_t pah[2][4];
            #pragma unroll
            for (int mg = 0; mg < 2; mg++)
                #pragma unroll
                for (int r = 0; r < 4; r++) {
                    int row = wbase + mg * 16 + g + ((r & 1) ? 8 : 0);
                    int col = kj * 8 + tg + ((r & 2) ? 4 : 0);
                    pah[mg][r] = __float_as_uint(sp[row][col]);
                }
            uint32_t vh[2][2];
            #pragma unroll
            for (int nt = 0; nt < 2; nt++)
                #pragma unroll
                for (int rr = 0; rr < 2; rr++)
                    vh[nt][rr] = __float_as_uint(sVh[kj * 8 + tg + rr * 4][nt * 8 + g]);
            #pragma unroll
            for (int mg = 0; mg < 2; mg++)
                #pragma unroll
                for (int nt = 0; nt < 2; nt++)
                    mma8(co[mg][nt], pah[mg], vh[nt]);
        }
        __syncthreads();
    }

    #pragma unroll
    for (int mg = 0; mg < 2; mg++)
        #pragma unroll
        for (int nt = 0; nt < 2; nt++) {
            int r0 = i0 + wbase + mg * 16 + g;
            int c  = nt * 8 + 2 * tg;
            *reinterpret_cast<float2*>(&g_pacc[js][n][r0][c]) =
                make_float2(co[mg][nt][0], co[mg][nt][1]);
            *reinterpret_cast<float2*>(&g_pacc[js][n][r0 + 8][c]) =
                make_float2(co[mg][nt][2], co[mg][nt][3]);
        }
    if (tg == 0) {
        #pragma unroll
        for (int mg = 0; mg < 2; mg++) {
            g_pl[js][n][i0 + wbase + mg * 16 + g]     = L[mg][0];
            g_pl[js][n][i0 + wbase + mg * 16 + g + 8] = L[mg][1];
        }
    }
}

// ======================================================================
// Kernel 3: combine (unchanged).
// ======================================================================
__global__ void combine_kernel(float* __restrict__ out)
{
    const int TOT  = NB * 2 * QC * 28 * 28;
    const int gidx = blockIdx.x * blockDim.x + threadIdx.x;
    if (gidx >= TOT * 4) return;
    const int e  = gidx >> 2;
    const int px = gidx & 3;

    int pw = e % 28;
    int t  = e / 28;
    int ph = t % 28; t /= 28;
    int c  = t % (2 * QC);
    int n  = t / (2 * QC);

    const int i = (2 * ph + (px >> 1)) * 56 + 2 * pw + (px & 1);

    float num = 0.f, den = 0.f;
    #pragma unroll
    for (int s = 0; s < JSPLIT; s++) {
        num += g_pacc[s][n][i][c];
        den += g_pl[s][n][i];
    }
    float r = num / den;
    r += __shfl_xor_sync(0xffffffffu, r, 1);
    r += __shfl_xor_sync(0xffffffffu, r, 2);
    if (px == 0) out[e] = 0.25f * r;
}

// ======================================================================
extern "C" void kernel_launch(void* const* d_in, const int* in_sizes, int n_in,
                              void* d_out, int out_size)
{
    const float* x     = (const float*)d_in[0];
    const float* w     = (const float*)d_in[1];
    const float* bq    = (const float*)d_in[2];
    const float* gamma = (const float*)d_in[3];
    const float* beta  = (const float*)d_in[4];
    const float* mean  = (const float*)d_in[5];
    const float* var   = (const float*)d_in[6];
    const float* rq    = (const float*)d_in[7];
    const float* rk    = (const float*)d_in[8];
    const float* rv    = (const float*)d_in[9];
    float* out = (float*)d_out;

    dim3 g1(HWP / QPIX, NB);          // (52, 4)
    qkv_kernel<<<g1, 256>>>(x, w, bq, gamma, beta, mean, var, rq, rk, rv);

    dim3 g2(HWP / 128, JSPLIT, NB);   // (26, 14, 4)
    attn_kernel<<<g2, 128>>>();

    const int TOT = NB * 2 * QC * 28 * 28;
    combine_kernel<<<(TOT * 4 + 255) / 256, 256>>>(out);
}

// round 12
// speedup vs baseline: 1.0509x; 1.0438x over previous
#include <cuda_runtime.h>
#include <math.h>
#include <stdint.h>

#define NB      4
#define IN_CHAN 128
#define HW      3136
#define HWP     3328      // 26*128 = 13*256 = 52*64
#define OC      32
#define QC      8
#define D       16
#define JSPLIT  14
#define JLEN    (HW / JSPLIT)   // 224
#define TJ      32
#define NT      (JLEN / TJ)     // 7 tiles
#define BN_EPS  1e-5f
#define QPIX    64
#define LOG2E   1.44269504088896340736f

#define SB_STRIDE 20      // 80B rows: 16B-aligned, conflict-free B-frag LDS
#define SP_STRIDE 36

// ---------------- scratch (device globals; no allocation allowed) ----------------
__device__ __align__(16) float g_A[NB][HWP][D];                 // log2e*[q+rk ; rq]
__device__ __align__(16) float g_B[NB][HWP][D];                 // [k ; q]
__device__ __align__(16) float g_V[NB][HWP][D];                 // v + rv
__device__ __align__(16) float g_pacc[JSPLIT][NB][HWP][D];      // partial sum(e^s * v)
__device__ __align__(16) float g_pl[JSPLIT][NB][HWP];           // partial sum(e^s)

// ---------------- helpers ----------------
__device__ __forceinline__ uint32_t f2tf(float f) {
    uint32_t r; asm("cvt.rna.tf32.f32 %0, %1;" : "=r"(r) : "f"(f)); return r;
}
__device__ __forceinline__ float ex2f(float x) {
    float r; asm("ex2.approx.ftz.f32 %0, %1;" : "=f"(r) : "f"(x)); return r;
}
__device__ __forceinline__ void mma8(float* d, const uint32_t* a, const uint32_t* b) {
    asm("mma.sync.aligned.m16n8k8.row.col.f32.tf32.tf32.f32 "
        "{%0,%1,%2,%3}, {%4,%5,%6,%7}, {%8,%9}, {%0,%1,%2,%3};"
        : "+f"(d[0]), "+f"(d[1]), "+f"(d[2]), "+f"(d[3])
        : "r"(a[0]), "r"(a[1]), "r"(a[2]), "r"(a[3]), "r"(b[0]), "r"(b[1]));
}
__device__ __forceinline__ void tfsplit(float x, uint32_t& hi, uint32_t& lo) {
    hi = f2tf(x);
    lo = f2tf(x - __uint_as_float(hi));
}
__device__ __forceinline__ void cpasync16(uint32_t saddr, const void* g) {
    asm volatile("cp.async.cg.shared.global [%0], [%1], 16;" :: "r"(saddr), "l"(g));
}
__device__ __forceinline__ void cpasync_commit() {
    asm volatile("cp.async.commit_group;" ::: "memory");
}
__device__ __forceinline__ void cpasync_wait1() {
    asm volatile("cp.async.wait_group 1;" ::: "memory");
}
__device__ __forceinline__ void cpasync_wait0() {
    asm volatile("cp.async.wait_group 0;" ::: "memory");
}

// ======================================================================
// Kernel 1: QKV 1x1 conv + BN + build A/B/V (unchanged R11, 15.7us).
// ======================================================================
__global__ __launch_bounds__(256)
void qkv_kernel(const float* __restrict__ x, const float* __restrict__ w,
                const float* __restrict__ bq, const float* __restrict__ gamma,
                const float* __restrict__ beta, const float* __restrict__ mean,
                const float* __restrict__ var,
                const float* __restrict__ rq, const float* __restrict__ rk,
                const float* __restrict__ rv)
{
    __shared__ float sx[IN_CHAN][QPIX];
    __shared__ float sw[IN_CHAN][OC];
    __shared__ float srk[QC][QPIX];
    __shared__ float srq[QC][QPIX];
    __shared__ float srv[2 * QC][QPIX];
    __shared__ float sscale[OC], sbias[OC];
    __shared__ float sr[QPIX][OC + 1];

    const int tid = threadIdx.x;
    const int p   = tid & (QPIX - 1);
    const int qd  = tid >> 6;

    const int n    = blockIdx.y;
    const int pix0 = blockIdx.x * QPIX;
    const bool live = (pix0 < HW);

    if (live) {
        const float* xb = x + (size_t)n * IN_CHAN * HW + pix0;
        #pragma unroll
        for (int k = 0; k < 8; k++) {
            int i = k * 256 + tid;
            int c = i >> 4, j = (i & 15) * 4;
            cpasync16((uint32_t)__cvta_generic_to_shared(&sx[c][j]),
                      xb + (size_t)c * HW + j);
        }
        #pragma unroll
        for (int k = 0; k < 2; k++) {
            int i = k * 256 + tid;
            int row = i >> 4, j = (i & 15) * 4;
            const float* gsrc;
            float* sdst;
            if (row < 8)       { gsrc = rk + (size_t)row * HW + pix0 + j;        sdst = &srk[row][j]; }
            else if (row < 16) { gsrc = rq + (size_t)(row - 8) * HW + pix0 + j;  sdst = &srq[row - 8][j]; }
            else               { gsrc = rv + (size_t)(row - 16) * HW + pix0 + j; sdst = &srv[row - 16][j]; }
            cpasync16((uint32_t)__cvta_generic_to_shared(sdst), gsrc);
        }
    }

    for (int idx = tid; idx < IN_CHAN * OC; idx += 256) {
        int o = idx & (OC - 1), c = idx >> 5;
        sw[c][o] = w[o * IN_CHAN + c];
    }
    if (tid < OC) {
        float sc = gamma[tid] * rsqrtf(var[tid] + BN_EPS);
        sscale[tid] = sc;
        sbias[tid]  = (bq[tid] - mean[tid]) * sc + beta[tid];
    }

    if (live) { cpasync_commit(); cpasync_wait0(); }
    __syncthreads();

    if (live) {
        const int obase = qd * 8;
        float acc[8];
        #pragma unroll
        for (int k = 0; k < 8; k++) acc[k] = 0.f;

        #pragma unroll 4
        for (int c = 0; c < IN_CHAN; c++) {
            const float xs = sx[c][p];
            float4 wa = *reinterpret_cast<const float4*>(&sw[c][obase]);
            float4 wb = *reinterpret_cast<const float4*>(&sw[c][obase + 4]);
            acc[0] = fmaf(xs, wa.x, acc[0]);
            acc[1] = fmaf(xs, wa.y, acc[1]);
            acc[2] = fmaf(xs, wa.z, acc[2]);
            acc[3] = fmaf(xs, wa.w, acc[3]);
            acc[4] = fmaf(xs, wb.x, acc[4]);
            acc[5] = fmaf(xs, wb.y, acc[5]);
            acc[6] = fmaf(xs, wb.z, acc[6]);
            acc[7] = fmaf(xs, wb.w, acc[7]);
        }
        #pragma unroll
        for (int k = 0; k < 8; k++)
            sr[p][obase + k] = fmaf(acc[k], sscale[obase + k], sbias[obase + k]);
    }
    __syncthreads();

    const int gpix = pix0 + p;
    if (live) {
        if (qd == 0) {
            float av[8];
            #pragma unroll
            for (int c = 0; c < 8; c++)
                av[c] = LOG2E * (sr[p][c] + srk[c][p]);
            reinterpret_cast<float4*>(&g_A[n][gpix][0])[0] = reinterpret_cast<float4*>(av)[0];
            reinterpret_cast<float4*>(&g_A[n][gpix][0])[1] = reinterpret_cast<float4*>(av)[1];
        } else if (qd == 1) {
            float av[8];
            #pragma unroll
            for (int c = 0; c < 8; c++)
                av[c] = LOG2E * srq[c][p];
            reinterpret_cast<float4*>(&g_A[n][gpix][8])[0] = reinterpret_cast<float4*>(av)[0];
            reinterpret_cast<float4*>(&g_A[n][gpix][8])[1] = reinterpret_cast<float4*>(av)[1];
        } else if (qd == 2) {
            float bv[16];
            #pragma unroll
            for (int c = 0; c < 8; c++) { bv[c] = sr[p][QC + c]; bv[QC + c] = sr[p][c]; }
            #pragma unroll
            for (int q4 = 0; q4 < 4; q4++)
                reinterpret_cast<float4*>(&g_B[n][gpix][0])[q4] = reinterpret_cast<float4*>(bv)[q4];
        } else {
            float vv[16];
            #pragma unroll
            for (int c = 0; c < 16; c++)
                vv[c] = sr[p][2 * QC + c] + srv[c][p];
            #pragma unroll
            for (int q4 = 0; q4 < 4; q4++)
                reinterpret_cast<float4*>(&g_V[n][gpix][0])[q4] = reinterpret_cast<float4*>(vv)[q4];
        }
    } else {
        float4 z = make_float4(0.f, 0.f, 0.f, 0.f);
        if (qd == 0) {
            reinterpret_cast<float4*>(&g_A[n][gpix][0])[0] = z;
            reinterpret_cast<float4*>(&g_A[n][gpix][0])[1] = z;
        } else if (qd == 1) {
            reinterpret_cast<float4*>(&g_A[n][gpix][8])[0] = z;
            reinterpret_cast<float4*>(&g_A[n][gpix][8])[1] = z;
        } else if (qd == 2) {
            #pragma unroll
            for (int q4 = 0; q4 < 4; q4++)
                reinterpret_cast<float4*>(&g_B[n][gpix][0])[q4] = z;
        } else {
            #pragma unroll
            for (int q4 = 0; q4 < 4; q4++)
                reinterpret_cast<float4*>(&g_V[n][gpix][0])[q4] = z;
        }
    }
}

// ======================================================================
// Kernel 2: tensor-core attention with cp.async 3-ring tile pipeline.
//   scores: tf32 x3 compensated   AV: tf32 x1, l over rounded P
// Raw B/V tiles in smem; tf32 split/round at fragment read.
// ONE __syncthreads per tile (3-buffer ring makes it legal: sync(t)
// implies all warps finished compute(t-2), whose buffer t+1 reuses).
// ======================================================================
__global__ __launch_bounds__(128)
void attn_kernel()
{
    __shared__ __align__(16) float sB[3][TJ][SB_STRIDE];   // raw B ring
    __shared__ __align__(16) float sV[3][TJ][SB_STRIDE];   // raw V ring
    __shared__ float sp[128][SP_STRIDE];

    const int tid   = threadIdx.x;
    const int warp  = tid >> 5;
    const int lane  = tid & 31;
    const int g     = lane >> 2;
    const int tg    = lane & 3;
    const int itile = blockIdx.x;
    const int js    = blockIdx.y;
    const int n     = blockIdx.z;
    const int i0    = itile * 128;
    const int wbase = warp * 32;
    const int jbase = js * JLEN;

    const int lr  = tid >> 2;           // tile row this thread loads
    const int lc4 = (tid & 3) * 4;      // tile col (16B chunk)

    // ---- persistent A fragments ----
    uint32_t ah[2][2][4], al[2][2][4];
    #pragma unroll
    for (int mg = 0; mg < 2; mg++)
        #pragma unroll
        for (int ks = 0; ks < 2; ks++)
            #pragma unroll
            for (int r = 0; r < 4; r++) {
                int row = i0 + wbase + mg * 16 + g + ((r & 1) ? 8 : 0);
                int col = ks * 8 + tg + ((r & 2) ? 4 : 0);
                tfsplit(g_A[n][row][col], ah[mg][ks][r], al[mg][ks][r]);
            }

    float co[2][2][4];
    #pragma unroll
    for (int mg = 0; mg < 2; mg++)
        #pragma unroll
        for (int nt = 0; nt < 2; nt++)
            #pragma unroll
            for (int r = 0; r < 4; r++) co[mg][nt][r] = 0.f;
    float L[2][2] = {{0.f, 0.f}, {0.f, 0.f}};

    // ---- prolog: issue tile 0 ----
    {
        const int j0 = jbase;
        cpasync16((uint32_t)__cvta_generic_to_shared(&sB[0][lr][lc4]),
                  &g_B[n][j0 + lr][lc4]);
        cpasync16((uint32_t)__cvta_generic_to_shared(&sV[0][lr][lc4]),
                  &g_V[n][j0 + lr][lc4]);
        cpasync_commit();
    }

    for (int t = 0; t < NT; t++) {
        // prefetch t+1 (ring slot (t+1)%3: last used by tile t-2, done by sync(t-1))
        if (t + 1 < NT) {
            const int jn = jbase + (t + 1) * TJ;
            const int nb = (t + 1) % 3;
            cpasync16((uint32_t)__cvta_generic_to_shared(&sB[nb][lr][lc4]),
                      &g_B[n][jn + lr][lc4]);
            cpasync16((uint32_t)__cvta_generic_to_shared(&sV[nb][lr][lc4]),
                      &g_V[n][jn + lr][lc4]);
            cpasync_commit();
            cpasync_wait1();            // tile t landed; t+1 still in flight
        } else {
            cpasync_wait0();
        }
        __syncthreads();
        const int buf = t % 3;

        // ---- scores: S[32i x 32j] per warp (x3 compensated), split at read ----
        float cs[2][4][4];
        #pragma unroll
        for (int mg = 0; mg < 2; mg++)
            #pragma unroll
            for (int nt = 0; nt < 4; nt++)
                #pragma unroll
                for (int r = 0; r < 4; r++) cs[mg][nt][r] = 0.f;

        #pragma unroll
        for (int ks = 0; ks < 2; ks++) {
            uint32_t bh[4][2], bl[4][2];
            #pragma unroll
            for (int nt = 0; nt < 4; nt++)
                #pragma unroll
                for (int rr = 0; rr < 2; rr++)
                    tfsplit(sB[buf][nt * 8 + g][ks * 8 + tg + rr * 4],
                            bh[nt][rr], bl[nt][rr]);
            #pragma unroll
            for (int mg = 0; mg < 2; mg++)
                #pragma unroll
                for (int nt = 0; nt < 4; nt++) {
                    mma8(cs[mg][nt], ah[mg][ks], bh[nt]);
                    mma8(cs[mg][nt], al[mg][ks], bh[nt]);
                    mma8(cs[mg][nt], ah[mg][ks], bl[nt]);
                }
        }

        // ---- exp2 -> round P -> row sums over rounded P -> stage ----
        #pragma unroll
        for (int mg = 0; mg < 2; mg++) {
            float s0 = 0.f, s1 = 0.f;
            #pragma unroll
            for (int nt = 0; nt < 4; nt++) {
                float p0 = __uint_as_float(f2tf(ex2f(cs[mg][nt][0])));
                float p1 = __uint_as_float(f2tf(ex2f(cs[mg][nt][1])));
                float p2 = __uint_as_float(f2tf(ex2f(cs[mg][nt][2])));
                float p3 = __uint_as_float(f2tf(ex2f(cs[mg][nt][3])));
                s0 += p0 + p1;
                s1 += p2 + p3;
                int r0 = wbase + mg * 16 + g;
                int c  = nt * 8 + 2 * tg;
                *reinterpret_cast<float2*>(&sp[r0][c])     = make_float2(p0, p1);
                *reinterpret_cast<float2*>(&sp[r0 + 8][c]) = make_float2(p2, p3);
            }
            s0 += __shfl_xor_sync(0xffffffffu, s0, 1);
            s0 += __shfl_xor_sync(0xffffffffu, s0, 2);
            s1 += __shfl_xor_sync(0xffffffffu, s1, 1);
            s1 += __shfl_xor_sync(0xffffffffu, s1, 2);
            L[mg][0] += s0;
            L[mg][1] += s1;
        }
        __syncwarp();

        // ---- AV: co += P x V, tf32 x1 (V rounded at read) ----
        #pragma unroll
        for (int kj = 0; kj < 4; kj++) {
            uint32_t pah[2][4];
            #pragma unroll
            for (int mg = 0; mg < 2; mg++)
                #pragma unroll
                for (int r = 0; r < 4; r++) {
                    int row = wbase + mg * 16 + g + ((r & 1) ? 8 : 0);
                    int col = kj * 8 + tg + ((r & 2) ? 4 : 0);
                    pah[mg][r] = __float_as_uint(sp[row][col]);
                }
            uint32_t vh[2][2];
            #pragma unroll
            for (int nt = 0; nt < 2; nt++)
                #pragma unroll
                for (int rr = 0; rr < 2; rr++)
                    vh[nt][rr] = f2tf(sV[buf][kj * 8 + tg + rr * 4][nt * 8 + g]);
            #pragma unroll
            for (int mg = 0; mg < 2; mg++)
                #pragma unroll
                for (int nt = 0; nt < 2; nt++)
                    mma8(co[mg][nt], pah[mg], vh[nt]);
        }
        // no end-of-tile sync: ring depth 3 + top-of-loop sync covers reuse
    }

    // ---- epilogue ----
    #pragma unroll
    for (int mg = 0; mg < 2; mg++)
        #pragma unroll
        for (int nt = 0; nt < 2; nt++) {
            int r0 = i0 + wbase + mg * 16 + g;
            int c  = nt * 8 + 2 * tg;
            *reinterpret_cast<float2*>(&g_pacc[js][n][r0][c]) =
                make_float2(co[mg][nt][0], co[mg][nt][1]);
            *reinterpret_cast<float2*>(&g_pacc[js][n][r0 + 8][c]) =
                make_float2(co[mg][nt][2], co[mg][nt][3]);
        }
    if (tg == 0) {
        #pragma unroll
        for (int mg = 0; mg < 2; mg++) {
            g_pl[js][n][i0 + wbase + mg * 16 + g]     = L[mg][0];
            g_pl[js][n][i0 + wbase + mg * 16 + g + 8] = L[mg][1];
        }
    }
}

// ======================================================================
// Kernel 3: combine (unchanged).
// ======================================================================
__global__ void combine_kernel(float* __restrict__ out)
{
    const int TOT  = NB * 2 * QC * 28 * 28;
    const int gidx = blockIdx.x * blockDim.x + threadIdx.x;
    if (gidx >= TOT * 4) return;
    const int e  = gidx >> 2;
    const int px = gidx & 3;

    int pw = e % 28;
    int t  = e / 28;
    int ph = t % 28; t /= 28;
    int c  = t % (2 * QC);
    int n  = t / (2 * QC);

    const int i = (2 * ph + (px >> 1)) * 56 + 2 * pw + (px & 1);

    float num = 0.f, den = 0.f;
    #pragma unroll
    for (int s = 0; s < JSPLIT; s++) {
        num += g_pacc[s][n][i][c];
        den += g_pl[s][n][i];
    }
    float r = num / den;
    r += __shfl_xor_sync(0xffffffffu, r, 1);
    r += __shfl_xor_sync(0xffffffffu, r, 2);
    if (px == 0) out[e] = 0.25f * r;
}

// ======================================================================
extern "C" void kernel_launch(void* const* d_in, const int* in_sizes, int n_in,
                              void* d_out, int out_size)
{
    const float* x     = (const float*)d_in[0];
    const float* w     = (const float*)d_in[1];
    const float* bq    = (const float*)d_in[2];
    const float* gamma = (const float*)d_in[3];
    const float* beta  = (const float*)d_in[4];
    const float* mean  = (const float*)d_in[5];
    const float* var   = (const float*)d_in[6];
    const float* rq    = (const float*)d_in[7];
    const float* rk    = (const float*)d_in[8];
    const float* rv    = (const float*)d_in[9];
    float* out = (float*)d_out;

    dim3 g1(HWP / QPIX, NB);          // (52, 4)
    qkv_kernel<<<g1, 256>>>(x, w, bq, gamma, beta, mean, var, rq, rk, rv);

    dim3 g2(HWP / 128, JSPLIT, NB);   // (26, 14, 4)
    attn_kernel<<<g2, 128>>>();

    const int TOT = NB * 2 * QC * 28 * 28;
    combine_kernel<<<(TOT * 4 + 255) / 256, 256>>>(out);
}